// round 5
// baseline (speedup 1.0000x reference)
#include <cuda_runtime.h>
#include <cuda_bf16.h>
#include <cstdint>

#define D      768
#define NTOK   16384            // 8 * 2048
#define NSPLIT 14
#define KT     64               // bf16 elems per k-tile = 128 B rows
#define KTILES (NTOK / KT)      // 256
#define NTILE  6
#define NPAIRS 21               // upper-triangular 128x128 tile pairs
#define NBLK   (NTOK / 64)

#define STAGES     3
#define TILE_B     (128 * 128)              // bytes per A (or B) stage tile
#define STAGE_B    (2 * TILE_B)             // A + B
#define SMEM_DYN   (STAGES * STAGE_B)       // 96 KB

// Scratch (allocation-free rule: __device__ globals)
__device__ __nv_bfloat16 g_Xt[(size_t)D * NTOK];
__device__ float         g_part[(size_t)NSPLIT * D * D];
__device__ float         g_colsq[(size_t)NBLK * D];

__device__ __forceinline__ uint32_t sw128(uint32_t off) {
    return off ^ ((off >> 3) & 0x70);
}

// ---------------------------------------------------------------------------
// Kernel 1: fp32 [N,768] -> bf16 transposed [768,N], fused fp32 column sum-sq
// ---------------------------------------------------------------------------
__global__ __launch_bounds__(256) void convert_kernel(const float* __restrict__ x) {
    __shared__ float tile[64][65];
    const int n0 = blockIdx.x * 64;
    const int c0 = blockIdx.y * 64;
    const int t  = threadIdx.x;

    const int fr = t >> 4;
    const int fc = t & 15;
    #pragma unroll
    for (int rr = 0; rr < 4; rr++) {
        const int r = fr + rr * 16;
        float4 v = *(const float4*)&x[(size_t)(n0 + r) * D + c0 + fc * 4];
        tile[r][fc * 4 + 0] = v.x;
        tile[r][fc * 4 + 1] = v.y;
        tile[r][fc * 4 + 2] = v.z;
        tile[r][fc * 4 + 3] = v.w;
    }
    __syncthreads();

    const int c   = t >> 2;
    const int seg = t & 3;
    float ssq = 0.f;
    __align__(16) __nv_bfloat16 vals[16];
    #pragma unroll
    for (int i = 0; i < 16; i++) {
        const float v = tile[seg * 16 + i][c];
        ssq += v * v;
        vals[i] = __float2bfloat16(v);
    }
    __nv_bfloat16* dst = &g_Xt[(size_t)(c0 + c) * NTOK + n0 + seg * 16];
    *(uint4*)(dst + 0) = *(uint4*)&vals[0];
    *(uint4*)(dst + 8) = *(uint4*)&vals[8];

    ssq += __shfl_xor_sync(0xffffffffu, ssq, 1);
    ssq += __shfl_xor_sync(0xffffffffu, ssq, 2);
    if (seg == 0) g_colsq[(size_t)blockIdx.x * D + c0 + c] = ssq;
}

// ---------------------------------------------------------------------------
// Kernel 2: split-K SYRK, 3-stage cp.async pipeline, SW128 smem, ldmatrix+mma
// grid = (21, 14), block = 256 (8 warps, 2x4 warp tiling of 128x128)
// ---------------------------------------------------------------------------
__global__ __launch_bounds__(256, 2) void gemm_kernel() {
    extern __shared__ __align__(1024) char smem[];

    const int tid = threadIdx.x;

    // upper-triangular tile map
    int trem = blockIdx.x, mi = 0;
    while (trem >= NTILE - mi) { trem -= NTILE - mi; mi++; }
    const int ni = mi + trem;
    const int m0 = mi * 128, n0 = ni * 128;

    // uneven split-K
    const int s   = blockIdx.y;
    const int kt0 = (s * KTILES) / NSPLIT;
    const int kt1 = ((s + 1) * KTILES) / NSPLIT;
    const int nit = kt1 - kt0;

    const int warp = tid >> 5, lane = tid & 31;
    const int wm = warp >> 2;   // 0..1
    const int wn = warp & 3;    // 0..3

    float acc[4][4][4];
    #pragma unroll
    for (int a = 0; a < 4; a++)
        #pragma unroll
        for (int b = 0; b < 4; b++)
            #pragma unroll
            for (int c = 0; c < 4; c++) acc[a][b][c] = 0.f;

    // --- producer mapping: thread t -> one 128-byte row per stage ---
    // t in [0,128): A row t ; t in [128,256): B row t-128
    const int prow  = tid & 127;
    const int isB   = tid >> 7;
    const __nv_bfloat16* gsrc =
        &g_Xt[(size_t)((isB ? n0 : m0) + prow) * NTOK];
    const uint32_t pmatoff = isB ? TILE_B : 0u;
    uint32_t pdst[8];
    #pragma unroll
    for (int c = 0; c < 8; c++)
        pdst[c] = pmatoff + sw128((uint32_t)(prow * 128 + c * 16));
    const uint32_t sbase = (uint32_t)__cvta_generic_to_shared(smem);

    // --- ldmatrix pre-swizzle base offsets (byte offset within stage) ---
    // A: per mf, row = wm*64 + mf*16 + (lane&15), kx = (lane>>4)*8
    uint32_t rowA[4];
    {
        const int r = lane & 15;
        #pragma unroll
        for (int mf = 0; mf < 4; mf++) rowA[mf] = (wm * 64 + mf * 16 + r) * 128;
    }
    const uint32_t kxA = ((lane >> 4) << 3) * 2;
    // B: per pair p2, row = wn*32 + (2*p2 + ((lane>>4)&1))*8 + (lane&7),
    //    ko = ((lane>>3)&1)*8
    uint32_t rowB[2];
    {
        const int r  = lane & 7;
        const int po = (lane >> 4) & 1;
        #pragma unroll
        for (int p2 = 0; p2 < 2; p2++)
            rowB[p2] = (wn * 32 + (2 * p2 + po) * 8 + r) * 128;
    }
    const uint32_t koB = (((lane >> 3) & 1) << 3) * 2;

    // --- prologue: issue stages 0 and 1 ---
    #pragma unroll
    for (int st = 0; st < 2; st++) {
        if (st < nit) {
            const __nv_bfloat16* src = gsrc + (size_t)(kt0 + st) * KT;
            const uint32_t dst0 = sbase + st * STAGE_B;
            #pragma unroll
            for (int c = 0; c < 8; c++) {
                asm volatile(
                    "cp.async.cg.shared.global [%0], [%1], 16;"
                    :: "r"(dst0 + pdst[c]), "l"(src + c * 8) : "memory");
            }
        }
        asm volatile("cp.async.commit_group;" ::: "memory");
    }

    int stage = 0;
    for (int it = 0; it < nit; ++it) {
        // drain groups so that stage `it` is resident (<=1 group outstanding)
        asm volatile("cp.async.wait_group 1;" ::: "memory");
        __syncthreads();

        // issue stage it+2 into the buffer freed at it-1
        {
            const int ft = it + 2;
            if (ft < nit) {
                const int fs = (stage + 2 >= STAGES) ? stage + 2 - STAGES : stage + 2;
                const __nv_bfloat16* src = gsrc + (size_t)(kt0 + ft) * KT;
                const uint32_t dst0 = sbase + fs * STAGE_B;
                #pragma unroll
                for (int c = 0; c < 8; c++) {
                    asm volatile(
                        "cp.async.cg.shared.global [%0], [%1], 16;"
                        :: "r"(dst0 + pdst[c]), "l"(src + c * 8) : "memory");
                }
            }
            asm volatile("cp.async.commit_group;" ::: "memory");
        }

        // compute on current stage
        const uint32_t bA = sbase + stage * STAGE_B;
        const uint32_t bB = bA + TILE_B;

        #pragma unroll
        for (int kk = 0; kk < KT; kk += 16) {
            uint32_t a[4][4], b[4][2];
            #pragma unroll
            for (int mf = 0; mf < 4; mf++) {
                const uint32_t ad = bA + sw128(rowA[mf] + kk * 2 + kxA);
                asm volatile(
                    "ldmatrix.sync.aligned.m8n8.x4.shared.b16 {%0,%1,%2,%3}, [%4];\n"
                    : "=r"(a[mf][0]), "=r"(a[mf][1]), "=r"(a[mf][2]), "=r"(a[mf][3])
                    : "r"(ad));
            }
            #pragma unroll
            for (int p2 = 0; p2 < 2; p2++) {
                const uint32_t bd = bB + sw128(rowB[p2] + kk * 2 + koB);
                asm volatile(
                    "ldmatrix.sync.aligned.m8n8.x4.shared.b16 {%0,%1,%2,%3}, [%4];\n"
                    : "=r"(b[2 * p2][0]), "=r"(b[2 * p2][1]),
                      "=r"(b[2 * p2 + 1][0]), "=r"(b[2 * p2 + 1][1])
                    : "r"(bd));
            }
            #pragma unroll
            for (int mf = 0; mf < 4; mf++)
                #pragma unroll
                for (int nf = 0; nf < 4; nf++) {
                    asm volatile(
                        "mma.sync.aligned.m16n8k16.row.col.f32.bf16.bf16.f32 "
                        "{%0,%1,%2,%3}, {%4,%5,%6,%7}, {%8,%9}, {%0,%1,%2,%3};\n"
                        : "+f"(acc[mf][nf][0]), "+f"(acc[mf][nf][1]),
                          "+f"(acc[mf][nf][2]), "+f"(acc[mf][nf][3])
                        : "r"(a[mf][0]), "r"(a[mf][1]), "r"(a[mf][2]), "r"(a[mf][3]),
                          "r"(b[nf][0]), "r"(b[nf][1]));
                }
        }

        // all warps must finish reading this stage before it is refilled (it+1's prefetch)
        __syncthreads();
        stage = (stage + 1 == STAGES) ? 0 : stage + 1;
    }

    // epilogue: write partial tile
    const int lg = lane >> 2, tg = lane & 3;
    float* outp = &g_part[(size_t)s * D * D];
    #pragma unroll
    for (int mf = 0; mf < 4; mf++) {
        #pragma unroll
        for (int nf = 0; nf < 4; nf++) {
            const int row = m0 + wm * 64 + mf * 16 + lg;
            const int col = n0 + wn * 32 + nf * 8 + 2 * tg;
            *(float2*)&outp[(size_t)row * D + col]       = make_float2(acc[mf][nf][0], acc[mf][nf][1]);
            *(float2*)&outp[(size_t)(row + 8) * D + col] = make_float2(acc[mf][nf][2], acc[mf][nf][3]);
        }
    }
}

// ---------------------------------------------------------------------------
// Kernel 3: reduce splits (mirroring lower triangle), scale, subtract;
// diagonal from exact fp32 sum-sq
// ---------------------------------------------------------------------------
__global__ __launch_bounds__(256) void final_kernel(float* __restrict__ out) {
    const int idx = blockIdx.x * 256 + threadIdx.x;
    if (idx >= D * D) return;
    const int i = idx / D;
    const int j = idx % D;
    const float inv_n = 1.0f / (float)NTOK;
    float v;
    if (i == j) {
        float ms = 0.f;
        for (int b = 0; b < NBLK; b++) ms += g_colsq[(size_t)b * D + i];
        v = 0.5f * (ms * inv_n) - 0.5f;
    } else {
        const int src = ((i >> 7) <= (j >> 7)) ? (i * D + j) : (j * D + i);
        float ssum = 0.f;
        #pragma unroll
        for (int sp = 0; sp < NSPLIT; sp++) ssum += g_part[(size_t)sp * D * D + src];
        v = 0.5f * (ssum * inv_n) - 0.5f;
    }
    out[idx] = v;
}

// ---------------------------------------------------------------------------
extern "C" void kernel_launch(void* const* d_in, const int* in_sizes, int n_in,
                              void* d_out, int out_size) {
    const float* x = (const float*)d_in[0];
    float* out = (float*)d_out;
    (void)in_sizes; (void)n_in; (void)out_size;

    cudaFuncSetAttribute(gemm_kernel,
                         cudaFuncAttributeMaxDynamicSharedMemorySize, SMEM_DYN);

    convert_kernel<<<dim3(NTOK / 64, D / 64), 256>>>(x);
    gemm_kernel<<<dim3(NPAIRS, NSPLIT), 256, SMEM_DYN>>>();
    final_kernel<<<(D * D + 255) / 256, 256>>>(out);
}